// round 3
// baseline (speedup 1.0000x reference)
#include <cuda_runtime.h>
#include <math.h>

#define MEM_DIM 2000
#define FEA     512
#define NB      32
#define HW      1024
#define NTOK    (NB * HW)      // 32768
#define THRES   0.0025f
#define EPSV    1e-12f
#define FIX_CAP 65536

// ---------------- scratch (static device allocations) ----------------
__device__ float  g_E[(size_t)NTOK * MEM_DIM];   // exp(logits), 262 MB
__device__ float  g_invS[NTOK];
__device__ double g_S64[NTOK];
__device__ float  g_invT[NTOK];
__device__ unsigned g_fix[FIX_CAP];
__device__ unsigned g_nfix;

// ---------------- packed f32x2 helpers ----------------
__device__ __forceinline__ unsigned long long pack2(float v) {
    unsigned long long r;
    unsigned u = __float_as_uint(v);
    asm("mov.b64 %0, {%1, %1};" : "=l"(r) : "r"(u));
    return r;
}
__device__ __forceinline__ void fma2(unsigned long long &c, unsigned long long a, unsigned long long b) {
    asm("fma.rn.f32x2 %0, %1, %2, %0;" : "+l"(c) : "l"(a), "l"(b));
}
__device__ __forceinline__ float lo2(unsigned long long v) { return __uint_as_float((unsigned)v); }
__device__ __forceinline__ float hi2(unsigned long long v) { return __uint_as_float((unsigned)(v >> 32)); }

// ---------------- kernel A: logits GEMM + exp ----------------
// E[n, m] = exp( sum_c xf[n,c] * W[m,c] ), xf[n,c] = x[b, c, hw], n = b*1024 + hw
#define BM 128
#define BN 128
#define BKK 16

__global__ __launch_bounds__(256, 2) void k_gemm_exp(const float* __restrict__ x,
                                                     const float* __restrict__ w) {
    __shared__ float As[BKK][BM];
    __shared__ float Bs[BKK][BN];
    const int tid = threadIdx.x;
    const int tx = tid & 15;          // column group (m)
    const int ty = tid >> 4;          // row group (n)
    const int m0 = blockIdx.x * BN;
    const int n0 = blockIdx.y * BM;
    const int b  = n0 >> 10;
    const int hw0 = n0 & 1023;
    const float* xb = x + (size_t)b * FEA * HW + hw0;

    unsigned long long acc[8][4];
#pragma unroll
    for (int i = 0; i < 8; i++)
#pragma unroll
        for (int j = 0; j < 4; j++) acc[i][j] = 0ull;

    for (int k0 = 0; k0 < FEA; k0 += BKK) {
#pragma unroll
        for (int p = 0; p < 2; p++) {
            int q = tid + p * 256;
            int c = q >> 5;
            int seg = q & 31;
            float4 v = *(const float4*)(xb + (size_t)(k0 + c) * HW + seg * 4);
            *(float4*)&As[c][seg * 4] = v;
        }
#pragma unroll
        for (int p = 0; p < 2; p++) {
            int q = tid + p * 256;
            int ml = q >> 2;
            int c4 = q & 3;
            int m = m0 + ml;
            float4 v = make_float4(0.f, 0.f, 0.f, 0.f);
            if (m < MEM_DIM) v = *(const float4*)(w + (size_t)m * FEA + k0 + c4 * 4);
            Bs[c4 * 4 + 0][ml] = v.x;
            Bs[c4 * 4 + 1][ml] = v.y;
            Bs[c4 * 4 + 2][ml] = v.z;
            Bs[c4 * 4 + 3][ml] = v.w;
        }
        __syncthreads();
#pragma unroll
        for (int k = 0; k < BKK; k++) {
            float4 a0 = *(const float4*)&As[k][ty * 8];
            float4 a1 = *(const float4*)&As[k][ty * 8 + 4];
            const unsigned long long* bp = (const unsigned long long*)&Bs[k][tx * 8];
            unsigned long long b0 = bp[0], b1 = bp[1], b2 = bp[2], b3 = bp[3];
            float av[8] = {a0.x, a0.y, a0.z, a0.w, a1.x, a1.y, a1.z, a1.w};
#pragma unroll
            for (int i = 0; i < 8; i++) {
                unsigned long long ap = pack2(av[i]);
                fma2(acc[i][0], ap, b0);
                fma2(acc[i][1], ap, b1);
                fma2(acc[i][2], ap, b2);
                fma2(acc[i][3], ap, b3);
            }
        }
        __syncthreads();
    }
    const int m = m0 + tx * 8;
    if (m < MEM_DIM) {
#pragma unroll
        for (int i = 0; i < 8; i++) {
            int n = n0 + ty * 8 + i;
            float4 o0, o1;
            o0.x = expf(lo2(acc[i][0])); o0.y = expf(hi2(acc[i][0]));
            o0.z = expf(lo2(acc[i][1])); o0.w = expf(hi2(acc[i][1]));
            o1.x = expf(lo2(acc[i][2])); o1.y = expf(hi2(acc[i][2]));
            o1.z = expf(lo2(acc[i][3])); o1.w = expf(hi2(acc[i][3]));
            float* dst = &g_E[(size_t)n * MEM_DIM + m];
            *(float4*)dst = o0;
            *(float4*)(dst + 4) = o1;
        }
    }
}

// ---------------- kernel B1: softmax denominators (fp64 accumulate) ----------------
__global__ __launch_bounds__(256) void k_rowsum() {
    int n = blockIdx.x * 8 + (threadIdx.x >> 5);
    int lane = threadIdx.x & 31;
    const float* row = g_E + (size_t)n * MEM_DIM;
    double s = 0.0;
    for (int j = lane; j < MEM_DIM; j += 32) s += (double)row[j];
#pragma unroll
    for (int o = 16; o; o >>= 1) s += __shfl_xor_sync(0xffffffffu, s, o);
    if (lane == 0) {
        g_S64[n]  = s;
        g_invS[n] = (float)(1.0 / s);
    }
}

// ---------------- counter reset ----------------
__global__ void k_reset() { g_nfix = 0u; }

// ---------------- kernel B1b: flag borderline values ----------------
// |att - THRES| < 5e-7  (≈ 2e-4 relative) -> needs fp64 refinement
__global__ __launch_bounds__(256) void k_scan() {
    int n = blockIdx.x;
    float is = g_invS[n];
    const float* row = g_E + (size_t)n * MEM_DIM;
    for (int j = threadIdx.x; j < MEM_DIM; j += 256) {
        float att = row[j] * is;
        if (fabsf(att - THRES) < 5e-7f) {
            unsigned idx = atomicAdd(&g_nfix, 1u);
            if (idx < FIX_CAP) g_fix[idx] = ((unsigned)n << 11) | (unsigned)j;
        }
    }
}

// ---------------- kernel B1c: fp64 refinement of borderline values ----------------
__global__ __launch_bounds__(256) void k_refine(const float* __restrict__ x,
                                                const float* __restrict__ w) {
    unsigned total = g_nfix;
    if (total > FIX_CAP) total = FIX_CAP;
    int lane = threadIdx.x & 31;
    int warp = (blockIdx.x * 256 + threadIdx.x) >> 5;
    const int nwarps = 64 * 8;   // 64 blocks * 8 warps
    for (unsigned i = warp; i < total; i += nwarps) {
        unsigned code = g_fix[i];
        int n = code >> 11;
        int m = code & 2047;
        int b = n >> 10, hw = n & 1023;
        const float* xr = x + (size_t)b * FEA * HW + hw;
        const float* wr = w + (size_t)m * FEA;
        double s = 0.0;
#pragma unroll
        for (int k = 0; k < 16; k++) {
            int c = lane * 16 + k;
            s += (double)xr[(size_t)c * HW] * (double)wr[c];
        }
#pragma unroll
        for (int o = 16; o; o >>= 1) s += __shfl_xor_sync(0xffffffffu, s, o);
        if (lane == 0) {
            double S = g_S64[n];
            double att = exp(s) / S;
            const double T = 0.0025, MARGIN = 5e-9;
            double att_f = att;
            if (att > T) { if (att < T + MARGIN) att_f = T + MARGIN; }
            else         { if (att > T - MARGIN) att_f = T - MARGIN; }
            g_E[(size_t)n * MEM_DIM + m] = (float)(att_f * S);
        }
    }
}

// ---------------- kernel B2: shrink L1 norms ----------------
__global__ __launch_bounds__(256) void k_rownorm() {
    int n = blockIdx.x * 8 + (threadIdx.x >> 5);
    int lane = threadIdx.x & 31;
    const float* row = g_E + (size_t)n * MEM_DIM;
    float is = g_invS[n];
    float t = 0.f;
    for (int j = lane; j < MEM_DIM; j += 32) {
        float att = row[j] * is;
        float d = att - THRES;
        if (d > 0.f) t += d * att / (d + EPSV);
    }
#pragma unroll
    for (int o = 16; o; o >>= 1) t += __shfl_xor_sync(0xffffffffu, t, o);
    if (lane == 0) g_invT[n] = 1.0f / fmaxf(t, EPSV);
}

// ---------------- kernel C: att output (transposed to NCHW) ----------------
__global__ __launch_bounds__(256) void k_att_out(float* __restrict__ att_out) {
    __shared__ float s[32][65];
    int m0  = blockIdx.x * 64;
    int hw0 = blockIdx.y * 32;
    int b   = blockIdx.z;
    int n0  = b * HW + hw0;
    for (int idx = threadIdx.x; idx < 32 * 64; idx += 256) {
        int i = idx >> 6, j = idx & 63;
        int m = m0 + j;
        float o = 0.f;
        if (m < MEM_DIM) {
            int n = n0 + i;
            float att = g_E[(size_t)n * MEM_DIM + m] * g_invS[n];
            float d = att - THRES;
            if (d > 0.f) o = (d * att / (d + EPSV)) * g_invT[n];
        }
        s[i][j] = o;
    }
    __syncthreads();
    for (int idx = threadIdx.x; idx < 32 * 64; idx += 256) {
        int j = idx >> 5, i = idx & 31;
        int m = m0 + j;
        if (m < MEM_DIM)
            att_out[((size_t)b * MEM_DIM + m) * HW + hw0 + i] = s[i][j];
    }
}

// ---------------- kernel D: sparse y = att' @ W (deterministic scan) ----------------
__global__ __launch_bounds__(256) void k_y(const float* __restrict__ w,
                                           float* __restrict__ y_out) {
    __shared__ float ys[8][513];
    int n0 = blockIdx.x * 8;
    int b = n0 >> 10, hw0 = n0 & 1023;
    int wid = threadIdx.x >> 5, lane = threadIdx.x & 31;
    int n = n0 + wid;
    float is = g_invS[n], it = g_invT[n];
#pragma unroll
    for (int k = 0; k < 16; k++) ys[wid][lane + k * 32] = 0.f;
    const float* row = g_E + (size_t)n * MEM_DIM;
    for (int j0 = 0; j0 < MEM_DIM; j0 += 32) {
        int m = j0 + lane;
        float e = (m < MEM_DIM) ? row[m] : 0.f;
        float att = e * is;
        float d = att - THRES;
        unsigned hits = __ballot_sync(0xffffffffu, d > 0.f);
        while (hits) {
            int bit = __ffs(hits) - 1;
            hits &= hits - 1;
            float ad = __shfl_sync(0xffffffffu, d, bit);
            float aa = __shfl_sync(0xffffffffu, att, bit);
            float av = (ad * aa / (ad + EPSV)) * it;
            const float* wr = w + (size_t)(j0 + bit) * FEA;
#pragma unroll
            for (int k = 0; k < 16; k++)
                ys[wid][lane + k * 32] += av * wr[lane + k * 32];
        }
    }
    __syncthreads();
    for (int idx = threadIdx.x; idx < 8 * FEA; idx += 256) {
        int i = idx & 7, c = idx >> 3;
        y_out[(size_t)b * FEA * HW + (size_t)c * HW + hw0 + i] = ys[i][c];
    }
}

// ---------------- launcher ----------------
extern "C" void kernel_launch(void* const* d_in, const int* in_sizes, int n_in,
                              void* d_out, int out_size) {
    const float* x = (const float*)d_in[0];
    const float* w = (const float*)d_in[1];
    if (n_in >= 2 && in_sizes[0] == MEM_DIM * FEA && in_sizes[1] != MEM_DIM * FEA) {
        const float* t = x; x = w; w = t;
    }
    float* y_out   = (float*)d_out;                       // 32*512*32*32
    float* att_out = y_out + (size_t)NB * FEA * HW;       // 32*2000*32*32

    dim3 gA((MEM_DIM + BN - 1) / BN, NTOK / BM);          // (16, 256)
    k_gemm_exp<<<gA, 256>>>(x, w);
    k_rowsum<<<NTOK / 8, 256>>>();
    k_reset<<<1, 1>>>();
    k_scan<<<NTOK, 256>>>();
    k_refine<<<64, 256>>>(x, w);
    k_rownorm<<<NTOK / 8, 256>>>();
    k_att_out<<<dim3((MEM_DIM + 63) / 64, HW / 32, NB), 256>>>(att_out);
    k_y<<<NTOK / 8, 256>>>(w, y_out);
}